// round 3
// baseline (speedup 1.0000x reference)
#include <cuda_runtime.h>
#include <math.h>

#define N_NODES 100000
#define N_EDGES 3200000

// Scratch (allocation-free rule: __device__ globals)
__device__ int   g_deg[N_NODES];
__device__ float g_dinv[N_NODES];
__device__ float g_h0[N_NODES * 16];   // x @ W1
__device__ float g_h1[N_NODES * 16];   // spmm1 accumulator
__device__ float g_h2[N_NODES * 40];   // relu(h1+b1) @ W2

// ---------------------------------------------------------------- utilities
__device__ __forceinline__ void red_add_v4(float* addr, float a, float b, float c, float d) {
    asm volatile("red.global.add.v4.f32 [%0], {%1,%2,%3,%4};"
                 :: "l"(addr), "f"(a), "f"(b), "f"(c), "f"(d) : "memory");
}

// ---------------------------------------------------------------- degree / dinv
__global__ void k_init_deg() {
    int i = blockIdx.x * blockDim.x + threadIdx.x;
    if (i < N_NODES) g_deg[i] = 1;          // self loop
}

__global__ void k_count(const int* __restrict__ ei) {
    int e = blockIdx.x * blockDim.x + threadIdx.x;
    if (e < N_EDGES) atomicAdd(&g_deg[ei[e]], 1);
}

__global__ void k_dinv() {
    int i = blockIdx.x * blockDim.x + threadIdx.x;
    if (i < N_NODES) g_dinv[i] = rsqrtf((float)g_deg[i]);
}

// ---------------------------------------------------------------- GEMM1: h0 = x @ W1 (100000x512 @ 512x16)
// block = 128 threads (4 warps). Each thread computes 2 rows x 16 cols.
// Rows per block = 4 warps * 64 = 256.
__global__ void __launch_bounds__(128) k_gemm1(const float* __restrict__ x,
                                               const float* __restrict__ W1) {
    __shared__ float4 W1s[2048];            // 512 x 16 fp32 = 32 KB, [k][c4]
    const float4* w4 = (const float4*)W1;
    for (int i = threadIdx.x; i < 2048; i += 128) W1s[i] = w4[i];
    __syncthreads();

    int warp = threadIdx.x >> 5, lane = threadIdx.x & 31;
    int r0 = blockIdx.x * 256 + warp * 64 + lane;
    int r1 = r0 + 32;
    bool v0 = r0 < N_NODES, v1 = r1 < N_NODES;
    const float4* xp0 = (const float4*)(x + (size_t)(v0 ? r0 : 0) * 512);
    const float4* xp1 = (const float4*)(x + (size_t)(v1 ? r1 : 0) * 512);

    float acc0[16], acc1[16];
#pragma unroll
    for (int c = 0; c < 16; c++) { acc0[c] = 0.f; acc1[c] = 0.f; }

#pragma unroll 4
    for (int k4 = 0; k4 < 128; k4++) {
        float4 xv0 = xp0[k4];
        float4 xv1 = xp1[k4];
#pragma unroll
        for (int kk = 0; kk < 4; kk++) {
            float a0 = (kk == 0) ? xv0.x : (kk == 1) ? xv0.y : (kk == 2) ? xv0.z : xv0.w;
            float a1 = (kk == 0) ? xv1.x : (kk == 1) ? xv1.y : (kk == 2) ? xv1.z : xv1.w;
            int kb = (k4 * 4 + kk) * 4;
#pragma unroll
            for (int c4 = 0; c4 < 4; c4++) {
                float4 w = W1s[kb + c4];
                acc0[c4 * 4 + 0] += a0 * w.x;
                acc0[c4 * 4 + 1] += a0 * w.y;
                acc0[c4 * 4 + 2] += a0 * w.z;
                acc0[c4 * 4 + 3] += a0 * w.w;
                acc1[c4 * 4 + 0] += a1 * w.x;
                acc1[c4 * 4 + 1] += a1 * w.y;
                acc1[c4 * 4 + 2] += a1 * w.z;
                acc1[c4 * 4 + 3] += a1 * w.w;
            }
        }
    }
    if (v0) {
        float4* o = (float4*)(g_h0 + (size_t)r0 * 16);
#pragma unroll
        for (int c4 = 0; c4 < 4; c4++)
            o[c4] = make_float4(acc0[c4 * 4 + 0], acc0[c4 * 4 + 1], acc0[c4 * 4 + 2], acc0[c4 * 4 + 3]);
    }
    if (v1) {
        float4* o = (float4*)(g_h0 + (size_t)r1 * 16);
#pragma unroll
        for (int c4 = 0; c4 < 4; c4++)
            o[c4] = make_float4(acc1[c4 * 4 + 0], acc1[c4 * 4 + 1], acc1[c4 * 4 + 2], acc1[c4 * 4 + 3]);
    }
}

// ---------------------------------------------------------------- self-loop init: h1 = dinv^2 * h0
__global__ void k_selfloop1() {
    int idx = blockIdx.x * blockDim.x + threadIdx.x;
    if (idx < N_NODES * 16) {
        int i = idx >> 4;
        float d = g_dinv[i];
        g_h1[idx] = d * d * g_h0[idx];
    }
}

// ---------------------------------------------------------------- SpMM1: h1[row] += w * h0[col]  (16 cols)
__global__ void k_spmm1(const int* __restrict__ ei) {
    int e = blockIdx.x * blockDim.x + threadIdx.x;
    if (e >= N_EDGES) return;
    int r = ei[e];
    int c = ei[e + N_EDGES];
    float w = g_dinv[r] * g_dinv[c];
    const float4* s = (const float4*)(g_h0 + (size_t)c * 16);
    float* d = g_h1 + (size_t)r * 16;
#pragma unroll
    for (int i = 0; i < 4; i++) {
        float4 v = s[i];
        red_add_v4(d + i * 4, w * v.x, w * v.y, w * v.z, w * v.w);
    }
}

// ---------------------------------------------------------------- GEMM2: h2 = relu(h1 + b1) @ W2  (16 -> 40)
// block = 128 threads, each thread 2 rows x 40 cols; rows/block = 256
__global__ void __launch_bounds__(128) k_gemm2(const float* __restrict__ W2,
                                               const float* __restrict__ b1) {
    __shared__ float4 W2s[160];             // 16 x 40 fp32, [c][j4]
    __shared__ float b1s[16];
    for (int i = threadIdx.x; i < 160; i += 128) W2s[i] = ((const float4*)W2)[i];
    if (threadIdx.x < 16) b1s[threadIdx.x] = b1[threadIdx.x];
    __syncthreads();

    int r0 = blockIdx.x * 256 + threadIdx.x;
    int r1 = r0 + 128;
    bool v0 = r0 < N_NODES, v1 = r1 < N_NODES;

    float acc0[40], acc1[40];
#pragma unroll
    for (int j = 0; j < 40; j++) { acc0[j] = 0.f; acc1[j] = 0.f; }

#pragma unroll
    for (int c = 0; c < 16; c++) {
        float xa = v0 ? fmaxf(g_h1[(size_t)r0 * 16 + c] + b1s[c], 0.f) : 0.f;
        float xb = v1 ? fmaxf(g_h1[(size_t)r1 * 16 + c] + b1s[c], 0.f) : 0.f;
#pragma unroll
        for (int j4 = 0; j4 < 10; j4++) {
            float4 w = W2s[c * 10 + j4];
            acc0[j4 * 4 + 0] += xa * w.x;
            acc0[j4 * 4 + 1] += xa * w.y;
            acc0[j4 * 4 + 2] += xa * w.z;
            acc0[j4 * 4 + 3] += xa * w.w;
            acc1[j4 * 4 + 0] += xb * w.x;
            acc1[j4 * 4 + 1] += xb * w.y;
            acc1[j4 * 4 + 2] += xb * w.z;
            acc1[j4 * 4 + 3] += xb * w.w;
        }
    }
    if (v0) {
        float4* o = (float4*)(g_h2 + (size_t)r0 * 40);
#pragma unroll
        for (int j4 = 0; j4 < 10; j4++)
            o[j4] = make_float4(acc0[j4 * 4 + 0], acc0[j4 * 4 + 1], acc0[j4 * 4 + 2], acc0[j4 * 4 + 3]);
    }
    if (v1) {
        float4* o = (float4*)(g_h2 + (size_t)r1 * 40);
#pragma unroll
        for (int j4 = 0; j4 < 10; j4++)
            o[j4] = make_float4(acc1[j4 * 4 + 0], acc1[j4 * 4 + 1], acc1[j4 * 4 + 2], acc1[j4 * 4 + 3]);
    }
}

// ---------------------------------------------------------------- self-loop init: out = dinv^2 * h2
__global__ void k_selfloop2(float* __restrict__ out) {
    int idx = blockIdx.x * blockDim.x + threadIdx.x;
    if (idx < N_NODES * 40) {
        int i = idx / 40;
        float d = g_dinv[i];
        out[idx] = d * d * g_h2[idx];
    }
}

// ---------------------------------------------------------------- SpMM2: out[row] += w * h2[col]  (40 cols)
__global__ void k_spmm2(const int* __restrict__ ei, float* __restrict__ out) {
    int e = blockIdx.x * blockDim.x + threadIdx.x;
    if (e >= N_EDGES) return;
    int r = ei[e];
    int c = ei[e + N_EDGES];
    float w = g_dinv[r] * g_dinv[c];
    const float4* s = (const float4*)(g_h2 + (size_t)c * 40);
    float* d = out + (size_t)r * 40;
#pragma unroll
    for (int i = 0; i < 10; i++) {
        float4 v = s[i];
        red_add_v4(d + i * 4, w * v.x, w * v.y, w * v.z, w * v.w);
    }
}

// ---------------------------------------------------------------- log_softmax(out + b2) over 40 cols (warp per row)
__global__ void k_lsm(float* __restrict__ out, const float* __restrict__ b2) {
    int wg = (blockIdx.x * blockDim.x + threadIdx.x) >> 5;
    int lane = threadIdx.x & 31;
    if (wg >= N_NODES) return;
    float* p = out + (size_t)wg * 40;
    float v0 = p[lane] + b2[lane];
    float v1 = (lane < 8) ? p[32 + lane] + b2[32 + lane] : -INFINITY;
    float m = fmaxf(v0, v1);
#pragma unroll
    for (int o = 16; o; o >>= 1) m = fmaxf(m, __shfl_xor_sync(0xffffffffu, m, o));
    float s = expf(v0 - m) + ((lane < 8) ? expf(v1 - m) : 0.f);
#pragma unroll
    for (int o = 16; o; o >>= 1) s += __shfl_xor_sync(0xffffffffu, s, o);
    float L = m + logf(s);
    p[lane] = v0 - L;
    if (lane < 8) p[32 + lane] = v1 - L;
}

// ---------------------------------------------------------------- launch
extern "C" void kernel_launch(void* const* d_in, const int* in_sizes, int n_in,
                              void* d_out, int out_size) {
    const float* x  = (const float*)d_in[0];
    const float* W1 = (const float*)d_in[1];
    const float* b1 = (const float*)d_in[2];
    const float* W2 = (const float*)d_in[3];
    const float* b2 = (const float*)d_in[4];
    const int*   ei = (const int*)d_in[5];
    float* out = (float*)d_out;

    k_init_deg<<<(N_NODES + 255) / 256, 256>>>();
    k_count<<<(N_EDGES + 255) / 256, 256>>>(ei);
    k_dinv<<<(N_NODES + 255) / 256, 256>>>();

    k_gemm1<<<(N_NODES + 255) / 256, 128>>>(x, W1);
    k_selfloop1<<<(N_NODES * 16 + 255) / 256, 256>>>();
    k_spmm1<<<(N_EDGES + 255) / 256, 256>>>(ei);

    k_gemm2<<<(N_NODES + 255) / 256, 128>>>(W2, b1);
    k_selfloop2<<<(N_NODES * 40 + 255) / 256, 256>>>(out);
    k_spmm2<<<(N_EDGES + 255) / 256, 256>>>(ei, out);

    k_lsm<<<(N_NODES / 8) + 1, 256>>>(out, b2);
}

// round 5
// speedup vs baseline: 2.2839x; 2.2839x over previous
#include <cuda_runtime.h>
#include <math.h>

#define N_NODES 100000
#define N_EDGES 3200000
#define SCAN_B 1024
#define SCAN_G 98            // 98*1024 = 100352 >= N_NODES

// ---------------- scratch (__device__ globals; no allocs) ----------------
__device__ int   g_deg[N_NODES];
__device__ float g_dinv[N_NODES];
__device__ int   g_rowptr[N_NODES + 1];
__device__ int   g_cursor[N_NODES];
__device__ int   g_scan[SCAN_G * SCAN_B];
__device__ int   g_bsum[SCAN_G];
__device__ int   g_boff[SCAN_G];
__device__ int2  g_cw[N_EDGES];           // packed (col, w-bits)
__device__ float g_h0[N_NODES * 16];      // x @ W1
__device__ float g_r1[N_NODES * 16];      // relu(spmm1 + b1)
__device__ float g_t [N_NODES * 16];      // spmm2(r1)

// ---------------- degree / dinv ----------------
__global__ void k_zero_deg() {
    int i = blockIdx.x * blockDim.x + threadIdx.x;
    if (i < N_NODES) g_deg[i] = 0;
}
__global__ void k_count(const int* __restrict__ ei) {
    int e = blockIdx.x * blockDim.x + threadIdx.x;
    if (e < N_EDGES) atomicAdd(&g_deg[ei[e]], 1);
}
__global__ void k_dinv() {
    int i = blockIdx.x * blockDim.x + threadIdx.x;
    if (i < N_NODES) g_dinv[i] = rsqrtf((float)(g_deg[i] + 1));  // +1 self loop
}

// ---------------- scan (CSR rowptr over real-edge counts) ----------------
__global__ void __launch_bounds__(SCAN_B) k_scan1() {
    __shared__ int s[SCAN_B];
    int t = threadIdx.x;
    int i = blockIdx.x * SCAN_B + t;
    s[t] = (i < N_NODES) ? g_deg[i] : 0;
    __syncthreads();
#pragma unroll
    for (int off = 1; off < SCAN_B; off <<= 1) {
        int add = (t >= off) ? s[t - off] : 0;
        __syncthreads();
        s[t] += add;
        __syncthreads();
    }
    g_scan[i] = s[t];
    if (t == SCAN_B - 1) g_bsum[blockIdx.x] = s[t];
}
__global__ void k_scan2() {
    __shared__ int s[128];
    int t = threadIdx.x;
    s[t] = (t < SCAN_G) ? g_bsum[t] : 0;
    __syncthreads();
#pragma unroll
    for (int off = 1; off < 128; off <<= 1) {
        int add = (t >= off) ? s[t - off] : 0;
        __syncthreads();
        s[t] += add;
        __syncthreads();
    }
    if (t < SCAN_G) g_boff[t] = s[t] - g_bsum[t];  // exclusive
}
__global__ void __launch_bounds__(SCAN_B) k_scan3() {
    int i = blockIdx.x * SCAN_B + threadIdx.x;
    if (i < N_NODES) {
        int incl = g_scan[i] + g_boff[blockIdx.x];
        g_rowptr[i + 1] = incl;
        g_cursor[i] = incl - g_deg[i];
        if (i == 0) g_rowptr[0] = 0;
    }
}

// ---------------- scatter edges into CSR ----------------
__global__ void k_scatter(const int* __restrict__ ei) {
    int e = blockIdx.x * blockDim.x + threadIdx.x;
    if (e >= N_EDGES) return;
    int r = ei[e];
    int c = ei[e + N_EDGES];
    int pos = atomicAdd(&g_cursor[r], 1);
    float w = g_dinv[r] * g_dinv[c];
    g_cw[pos] = make_int2(c, __float_as_int(w));
}

// ---------------- GEMM1: h0 = x @ W1 (100000x512 @ 512x16) ----------------
// block 256 threads = 256 rows; K staged in chunks of 32 through smem.
#define G1_ROWS 256
#define G1_KC   32
__global__ void __launch_bounds__(256) k_gemm1(const float* __restrict__ x,
                                               const float* __restrict__ W1) {
    __shared__ float  xs[G1_ROWS][G1_KC + 1];   // stride 33: conflict-free
    __shared__ float4 w1s[G1_KC * 4];           // 32 k x 16 cols
    int tid = threadIdx.x;
    int row0 = blockIdx.x * G1_ROWS;
    int r = row0 + tid;

    float acc[16];
#pragma unroll
    for (int c = 0; c < 16; c++) acc[c] = 0.f;

    int f4 = tid & 7, rbase = tid >> 3;
    for (int s = 0; s < 512 / G1_KC; s++) {
        if (tid < G1_KC * 4) w1s[tid] = ((const float4*)W1)[s * G1_KC * 4 + tid];
        int rl = rbase;
#pragma unroll
        for (int i = 0; i < 8; i++, rl += 32) {
            int rr = row0 + rl;
            float4 v = make_float4(0.f, 0.f, 0.f, 0.f);
            if (rr < N_NODES) v = ((const float4*)(x + (size_t)rr * 512))[s * 8 + f4];
            xs[rl][f4 * 4 + 0] = v.x;
            xs[rl][f4 * 4 + 1] = v.y;
            xs[rl][f4 * 4 + 2] = v.z;
            xs[rl][f4 * 4 + 3] = v.w;
        }
        __syncthreads();
#pragma unroll
        for (int k = 0; k < G1_KC; k++) {
            float a = xs[tid][k];
#pragma unroll
            for (int c4 = 0; c4 < 4; c4++) {
                float4 w = w1s[k * 4 + c4];
                acc[c4 * 4 + 0] += a * w.x;
                acc[c4 * 4 + 1] += a * w.y;
                acc[c4 * 4 + 2] += a * w.z;
                acc[c4 * 4 + 3] += a * w.w;
            }
        }
        __syncthreads();
    }
    if (r < N_NODES) {
        float4* o = (float4*)(g_h0 + (size_t)r * 16);
#pragma unroll
        for (int c4 = 0; c4 < 4; c4++)
            o[c4] = make_float4(acc[c4 * 4], acc[c4 * 4 + 1], acc[c4 * 4 + 2], acc[c4 * 4 + 3]);
    }
}

// ---------------- gather SpMM (16-wide): 4 threads per row ----------------
// STAGE 1: g_r1 = relu(spmm(g_h0) + b1);  STAGE 2: g_t = spmm(g_r1)
// Globals referenced in DEVICE code only (host shadow addresses are bogus).
template <int STAGE>
__global__ void k_gather(const float* __restrict__ bias) {
    const float* __restrict__ src = (STAGE == 1) ? g_h0 : g_r1;
    float* __restrict__       dst = (STAGE == 1) ? g_r1 : g_t;
    int t = blockIdx.x * blockDim.x + threadIdx.x;
    int r = t >> 2, j = t & 3;
    if (r >= N_NODES) return;
    float d = g_dinv[r];
    const float4* s4 = (const float4*)src;
    float4 v = s4[r * 4 + j];
    float dd = d * d;
    float4 acc = make_float4(dd * v.x, dd * v.y, dd * v.z, dd * v.w);
    int e = g_rowptr[r], e1 = g_rowptr[r + 1];
#pragma unroll 4
    for (; e < e1; e++) {
        int2 cw = g_cw[e];
        float w = __int_as_float(cw.y);
        float4 h = s4[cw.x * 4 + j];
        acc.x += w * h.x;
        acc.y += w * h.y;
        acc.z += w * h.z;
        acc.w += w * h.w;
    }
    if (STAGE == 1) {
        float4 b = ((const float4*)bias)[j];
        acc.x = fmaxf(acc.x + b.x, 0.f);
        acc.y = fmaxf(acc.y + b.y, 0.f);
        acc.z = fmaxf(acc.z + b.z, 0.f);
        acc.w = fmaxf(acc.w + b.w, 0.f);
    }
    ((float4*)dst)[r * 4 + j] = acc;
}

// ---------------- fused GEMM2 + bias + log_softmax ----------------
// out = log_softmax(g_t @ W2 + b2); thread per row
__global__ void __launch_bounds__(256) k_gemm2lsm(const float* __restrict__ W2,
                                                  const float* __restrict__ b2,
                                                  float* __restrict__ out) {
    __shared__ float4 w2s[160];   // 16 x 40
    __shared__ float  b2s[40];
    for (int i = threadIdx.x; i < 160; i += 256) w2s[i] = ((const float4*)W2)[i];
    if (threadIdx.x < 40) b2s[threadIdx.x] = b2[threadIdx.x];
    __syncthreads();

    int r = blockIdx.x * blockDim.x + threadIdx.x;
    if (r >= N_NODES) return;

    float tv[16];
    const float4* tp = (const float4*)(g_t + (size_t)r * 16);
#pragma unroll
    for (int k4 = 0; k4 < 4; k4++) {
        float4 v = tp[k4];
        tv[k4 * 4 + 0] = v.x; tv[k4 * 4 + 1] = v.y;
        tv[k4 * 4 + 2] = v.z; tv[k4 * 4 + 3] = v.w;
    }

    float acc[40];
#pragma unroll
    for (int j = 0; j < 40; j++) acc[j] = b2s[j];
#pragma unroll
    for (int k = 0; k < 16; k++) {
        float a = tv[k];
#pragma unroll
        for (int j4 = 0; j4 < 10; j4++) {
            float4 w = w2s[k * 10 + j4];
            acc[j4 * 4 + 0] += a * w.x;
            acc[j4 * 4 + 1] += a * w.y;
            acc[j4 * 4 + 2] += a * w.z;
            acc[j4 * 4 + 3] += a * w.w;
        }
    }
    float m = acc[0];
#pragma unroll
    for (int j = 1; j < 40; j++) m = fmaxf(m, acc[j]);
    float s = 0.f;
#pragma unroll
    for (int j = 0; j < 40; j++) s += expf(acc[j] - m);
    float L = m + logf(s);
    float4* o = (float4*)(out + (size_t)r * 40);
#pragma unroll
    for (int j4 = 0; j4 < 10; j4++)
        o[j4] = make_float4(acc[j4 * 4] - L, acc[j4 * 4 + 1] - L,
                            acc[j4 * 4 + 2] - L, acc[j4 * 4 + 3] - L);
}

// ---------------- launch ----------------
extern "C" void kernel_launch(void* const* d_in, const int* in_sizes, int n_in,
                              void* d_out, int out_size) {
    const float* x  = (const float*)d_in[0];
    const float* W1 = (const float*)d_in[1];
    const float* b1 = (const float*)d_in[2];
    const float* W2 = (const float*)d_in[3];
    const float* b2 = (const float*)d_in[4];
    const int*   ei = (const int*)d_in[5];
    float* out = (float*)d_out;

    k_zero_deg<<<(N_NODES + 255) / 256, 256>>>();
    k_count<<<(N_EDGES + 255) / 256, 256>>>(ei);
    k_dinv<<<(N_NODES + 255) / 256, 256>>>();

    k_scan1<<<SCAN_G, SCAN_B>>>();
    k_scan2<<<1, 128>>>();
    k_scan3<<<SCAN_G, SCAN_B>>>();
    k_scatter<<<(N_EDGES + 255) / 256, 256>>>(ei);

    k_gemm1<<<(N_NODES + G1_ROWS - 1) / G1_ROWS, 256>>>(x, W1);

    k_gather<1><<<(N_NODES * 4 + 255) / 256, 256>>>(b1);
    k_gather<2><<<(N_NODES * 4 + 255) / 256, 256>>>(b1);

    k_gemm2lsm<<<(N_NODES + 255) / 256, 256>>>(W2, b2, out);
}